// round 10
// baseline (speedup 1.0000x reference)
#include <cuda_runtime.h>
#include <cuda_bf16.h>
#include <math.h>
#include <stdint.h>

// Problem constants (fixed by setup_inputs)
#define T_SEQ 2048
#define EMB   2048
#define NH    32
#define NKV   8
#define HD    64
#define NBLK  32
#define WIN   256
#define KVD   (NKV * HD)   // 512

// fp32 scratch
__device__ float g_q[T_SEQ * NH * HD];     // [t][h][d]
__device__ float g_k[T_SEQ * NKV * HD];    // [t][kv][d]
__device__ float g_v[T_SEQ * NKV * HD];
__device__ int   g_allow[NBLK * NBLK];

// bf16 hi/lo pre-converted operands
__device__ __nv_bfloat16 g_hsh[T_SEQ * EMB], g_hsl[T_SEQ * EMB];
__device__ __nv_bfloat16 g_wqh[EMB * EMB],  g_wql[EMB * EMB];
__device__ __nv_bfloat16 g_wkh[KVD * EMB],  g_wkl[KVD * EMB];
__device__ __nv_bfloat16 g_wvh[KVD * EMB],  g_wvl[KVD * EMB];
__device__ __nv_bfloat16 g_woh[EMB * EMB],  g_wol[EMB * EMB];
__device__ __nv_bfloat16 g_oh[T_SEQ * EMB], g_ol[T_SEQ * EMB];

// attention K/V bf16 hi/lo (K: [kv][t][d], V transposed: [kv][d][t])
__device__ __nv_bfloat16 g_kh[NKV * T_SEQ * HD], g_kl[NKV * T_SEQ * HD];
__device__ __nv_bfloat16 g_vh[NKV * HD * T_SEQ], g_vl[NKV * HD * T_SEQ];

// one extern-shared buffer shared by all dynamic-smem kernels
extern __shared__ char dsm_raw[];

// ---------------------------------------------------------------------------
// Decode rw_allow_blocks robustly (bool/int8 vs int32 vs float32).
// ---------------------------------------------------------------------------
__global__ void decode_mask_kernel(const void* p) {
    __shared__ int cnt0, cnt123;
    int tid = threadIdx.x;
    if (tid == 0) { cnt0 = 0; cnt123 = 0; }
    __syncthreads();
    const unsigned char* b = (const unsigned char*)p;
    int l0 = 0, l123 = 0;
    for (int i = tid; i < 1024; i += 256) {
        if (b[i]) { if ((i & 3) == 0) l0++; else l123++; }
    }
    atomicAdd(&cnt0, l0);
    atomicAdd(&cnt123, l123);
    __syncthreads();
    if (cnt123 == 0) {
        const int* a = (const int*)p;
        for (int i = tid; i < 1024; i += 256) g_allow[i] = (a[i] != 0);
    } else if (cnt0 == 0) {
        const float* a = (const float*)p;
        for (int i = tid; i < 1024; i += 256) g_allow[i] = (a[i] != 0.0f);
    } else {
        for (int i = tid; i < 1024; i += 256) g_allow[i] = (b[i] != 0);
    }
}

// ---------------------------------------------------------------------------
// Shared helpers
// ---------------------------------------------------------------------------
#define MMA_BF16(d, a0, a1, a2, a3, b0, b1)                                   \
    asm volatile(                                                             \
        "mma.sync.aligned.m16n8k16.row.col.f32.bf16.bf16.f32 "                \
        "{%0,%1,%2,%3}, {%4,%5,%6,%7}, {%8,%9}, {%0,%1,%2,%3};"               \
        : "+f"(d[0]), "+f"(d[1]), "+f"(d[2]), "+f"(d[3])                      \
        : "r"(a0), "r"(a1), "r"(a2), "r"(a3), "r"(b0), "r"(b1))

#define LDSM_X4(R0, R1, R2, R3, ADDR)                                         \
    asm volatile("ldmatrix.sync.aligned.m8n8.x4.shared.b16 {%0,%1,%2,%3}, [%4];" \
        : "=r"(R0), "=r"(R1), "=r"(R2), "=r"(R3) : "r"(ADDR))

#define LDSM_X2(R0, R1, ADDR)                                                 \
    asm volatile("ldmatrix.sync.aligned.m8n8.x2.shared.b16 {%0,%1}, [%2];"    \
        : "=r"(R0), "=r"(R1) : "r"(ADDR))

__device__ __forceinline__ void cp16(uint32_t saddr, const void* g) {
    asm volatile("cp.async.cg.shared.global [%0], [%1], 16;" :: "r"(saddr), "l"(g));
}
__device__ __forceinline__ void cp_commit() {
    asm volatile("cp.async.commit_group;" ::: "memory");
}

__device__ __forceinline__ void cvt2(float2 f, uint32_t& hi, uint32_t& lo) {
    __nv_bfloat162 h = __floats2bfloat162_rn(f.x, f.y);
    hi = *reinterpret_cast<uint32_t*>(&h);
    __nv_bfloat162 l = __floats2bfloat162_rn(f.x - __bfloat162float(h.x),
                                             f.y - __bfloat162float(h.y));
    lo = *reinterpret_cast<uint32_t*>(&l);
}

__device__ __forceinline__ uint32_t smem_u32(const void* p) {
    return (uint32_t)__cvta_generic_to_shared(p);
}

// fp32 -> bf16 hi/lo, 2 elements per thread
__global__ void cvt_hilo(const float* __restrict__ src,
                         __nv_bfloat16* __restrict__ h,
                         __nv_bfloat16* __restrict__ l, int n2) {
    int i = blockIdx.x * blockDim.x + threadIdx.x;
    if (i >= n2) return;
    float2 v = ((const float2*)src)[i];
    uint32_t hi, lo;
    cvt2(v, hi, lo);
    ((uint32_t*)h)[i] = hi;
    ((uint32_t*)l)[i] = lo;
}

// ---------------------------------------------------------------------------
// GEMM v5: C[M,N] = A[M,K] * B[N,K]^T, pre-split bf16 hi/lo, ldmatrix frags.
// CTA tile 128x256, warp tile 64x64 (8 warps), BK=32, 2-stage cp.async.
// 85B smem traffic per MMA (< 128 B/cyc crossbar at rt=4) -> tensor-bound.
// ---------------------------------------------------------------------------
#define ROW_B     80                        // bytes per smem row (64 data + 16 pad)
#define A_TILE_B  (128 * ROW_B)             // 10240 per h/l tile
#define B_TILE_B  (256 * ROW_B)             // 20480 per h/l tile
#define G5_STAGE  (2 * A_TILE_B + 2 * B_TILE_B)   // 61440
#define G5_SMEM   (2 * G5_STAGE)                  // 122880

__device__ __forceinline__ void gemm5_core(
    const __nv_bfloat16* __restrict__ Ah, const __nv_bfloat16* __restrict__ Al,
    const __nv_bfloat16* __restrict__ Bh, const __nv_bfloat16* __restrict__ Bl,
    float* __restrict__ C, int K, int ldc, int m0, int n0)
{
    uint32_t sbase = smem_u32(dsm_raw);

    int tid  = threadIdx.x;
    int warp = tid >> 5;
    int lane = tid & 31;
    int wm = warp & 1;      // 2 m-slots of 64
    int wn = warp >> 1;     // 4 n-slots of 64
    int qr = lane >> 2;
    int qc2 = (lane & 3) * 2;

    float acc[4][8][4];
#pragma unroll
    for (int i = 0; i < 4; i++)
#pragma unroll
        for (int j = 0; j < 8; j++)
#pragma unroll
            for (int e = 0; e < 4; e++) acc[i][j][e] = 0.0f;

    const __nv_bfloat16* aSrc[2] = { Ah + (size_t)m0 * K, Al + (size_t)m0 * K };
    const __nv_bfloat16* bSrc[2] = { Bh + (size_t)n0 * K, Bl + (size_t)n0 * K };

    // ldmatrix per-thread base byte offsets within a stage
    uint32_t aOff = (uint32_t)(wm * 64 + (lane & 7) + ((lane >> 3) & 1) * 8) * ROW_B
                  + ((lane >> 4) & 1) * 16;
    uint32_t bOff = (uint32_t)(wn * 64 + (lane & 7)) * ROW_B
                  + ((lane >> 3) & 1) * 16;

    const int NITER = K / 32;

    // stage fill: 3072 16B-chunks, 12 per thread, no intra-warp divergence
    auto fill = [&](int stage, int k0) {
        uint32_t sb = sbase + stage * G5_STAGE;
#pragma unroll
        for (int t = 0; t < 12; t++) {
            int id = t * 256 + tid;
            if (id < 1024) {             // A tiles (t = 0..3)
                int hl  = id >> 9;
                int row = (id >> 2) & 127;
                int c   = id & 3;
                cp16(sb + hl * A_TILE_B + row * ROW_B + c * 16,
                     aSrc[hl] + (size_t)row * K + k0 + c * 8);
            } else {                     // B tiles (t = 4..11)
                int idb = id - 1024;
                int hl  = idb >> 10;
                int row = (idb >> 2) & 255;
                int c   = idb & 3;
                cp16(sb + 2 * A_TILE_B + hl * B_TILE_B + row * ROW_B + c * 16,
                     bSrc[hl] + (size_t)row * K + k0 + c * 8);
            }
        }
        cp_commit();
    };

    fill(0, 0);

    for (int it = 0; it < NITER; it++) {
        if (it + 1 < NITER) {
            fill((it + 1) & 1, (it + 1) * 32);
            asm volatile("cp.async.wait_group 1;" ::: "memory");
        } else {
            asm volatile("cp.async.wait_group 0;" ::: "memory");
        }
        __syncthreads();

        uint32_t sb = sbase + (it & 1) * G5_STAGE;
        uint32_t tB = sb + 2 * A_TILE_B;

#pragma unroll
        for (int k1 = 0; k1 < 2; k1++) {
            uint32_t ko = k1 * 32;   // 16 halves
            uint32_t ah[4][4], al[4][4];
#pragma unroll
            for (int mi = 0; mi < 4; mi++) {
                uint32_t off = aOff + mi * (16 * ROW_B) + ko;
                LDSM_X4(ah[mi][0], ah[mi][1], ah[mi][2], ah[mi][3], sb + off);
                LDSM_X4(al[mi][0], al[mi][1], al[mi][2], al[mi][3], sb + A_TILE_B + off);
            }
#pragma unroll
            for (int ni = 0; ni < 8; ni++) {
                uint32_t boff = bOff + ni * (8 * ROW_B) + ko;
                uint32_t bh0, bh1, bl0, bl1;
                LDSM_X2(bh0, bh1, tB + boff);
                LDSM_X2(bl0, bl1, tB + B_TILE_B + boff);
#pragma unroll
                for (int mi = 0; mi < 4; mi++) {
                    MMA_BF16(acc[mi][ni], ah[mi][0], ah[mi][1], ah[mi][2], ah[mi][3], bh0, bh1);
                    MMA_BF16(acc[mi][ni], ah[mi][0], ah[mi][1], ah[mi][2], ah[mi][3], bl0, bl1);
                    MMA_BF16(acc[mi][ni], al[mi][0], al[mi][1], al[mi][2], al[mi][3], bh0, bh1);
                }
            }
        }
        __syncthreads();
    }

    // epilogue
#pragma unroll
    for (int mi = 0; mi < 4; mi++) {
#pragma unroll
        for (int ni = 0; ni < 8; ni++) {
            int r = m0 + wm * 64 + mi * 16 + qr;
            int cidx = n0 + wn * 64 + ni * 8 + qc2;
            *(float2*)&C[(size_t)r * ldc + cidx] =
                make_float2(acc[mi][ni][0], acc[mi][ni][1]);
            *(float2*)&C[(size_t)(r + 8) * ldc + cidx] =
                make_float2(acc[mi][ni][2], acc[mi][ni][3]);
        }
    }
}

// qkv grid: (12, 16). bx 0..7 -> Q (n0 = bx*256), 8..9 -> K, 10..11 -> V
__global__ __launch_bounds__(256, 1)
void qkv_gemm() {
    int bx = blockIdx.x;
    int m0 = blockIdx.y * 128;
    if (bx < 8)
        gemm5_core(g_hsh, g_hsl, g_wqh, g_wql, g_q, EMB, EMB, m0, bx * 256);
    else if (bx < 10)
        gemm5_core(g_hsh, g_hsl, g_wkh, g_wkl, g_k, EMB, KVD, m0, (bx - 8) * 256);
    else
        gemm5_core(g_hsh, g_hsl, g_wvh, g_wvl, g_v, EMB, KVD, m0, (bx - 10) * 256);
}

__global__ __launch_bounds__(256, 1)
void out_gemm(float* __restrict__ out) {
    gemm5_core(g_oh, g_ol, g_woh, g_wol, out, EMB, EMB,
               blockIdx.y * 128, blockIdx.x * 256);
}

// ---------------------------------------------------------------------------
// RoPE applied in-place to q and k.
// ---------------------------------------------------------------------------
__global__ void rope_kernel(const float* __restrict__ cosb, const float* __restrict__ sinb) {
    int idx = blockIdx.x * blockDim.x + threadIdx.x;
    const int total = T_SEQ * (NH + NKV) * 32;
    if (idx >= total) return;
    int d = idx & 31;
    int rest = idx >> 5;
    int head = rest % (NH + NKV);
    int t = rest / (NH + NKV);
    float c0 = cosb[t * HD + d];
    float s0 = sinb[t * HD + d];
    float c1 = cosb[t * HD + d + 32];
    float s1 = sinb[t * HD + d + 32];
    float* base = (head < NH) ? (g_q + ((size_t)t * NH + head) * HD)
                              : (g_k + ((size_t)t * NKV + (head - NH)) * HD);
    float x0 = base[d];
    float x1 = base[d + 32];
    base[d]      = x0 * c0 - x1 * s0;
    base[d + 32] = x1 * c1 + x0 * s1;
}

// ---------------------------------------------------------------------------
// Prep: K (post-RoPE) -> bf16 hi/lo [kv][t][d]; V -> transposed [kv][d][t].
// ---------------------------------------------------------------------------
__global__ void prep_k_kernel() {
    int o = blockIdx.x * blockDim.x + threadIdx.x;
    if (o >= NKV * T_SEQ * HD) return;
    int d  = o & 63;
    int t  = (o >> 6) & (T_SEQ - 1);
    int kv = o >> 17;
    float v = g_k[((size_t)t * NKV + kv) * HD + d];
    __nv_bfloat16 h = __float2bfloat16(v);
    g_kh[o] = h;
    g_kl[o] = __float2bfloat16(v - __bfloat162float(h));
}

__global__ void prep_v_kernel() {
    int o = blockIdx.x * blockDim.x + threadIdx.x;
    if (o >= NKV * HD * T_SEQ) return;
    int t  = o & (T_SEQ - 1);
    int d  = (o >> 11) & 63;
    int kv = o >> 17;
    float v = g_v[((size_t)t * NKV + kv) * HD + d];
    __nv_bfloat16 h = __float2bfloat16(v);
    g_vh[o] = h;
    g_vl[o] = __float2bfloat16(v - __bfloat162float(h));
}

// ---------------------------------------------------------------------------
// MMA flash attention with double-buffered kb tiles (dynamic smem, 2 stages).
// ---------------------------------------------------------------------------
#define TSTR 72
#define ATT_TILE   (64 * TSTR)
#define ATT_STAGE  (4 * ATT_TILE)
#define ATT_SMEM   (2 * ATT_STAGE * 2)

__device__ __forceinline__ void att_issue_loads(__nv_bfloat16* att_dsm,
                                                int stage, int kb, int kv, int tid) {
    uint32_t base = smem_u32(att_dsm + stage * ATT_STAGE);
#pragma unroll
    for (int t = 0; t < 16; t++) {
        int id   = t * 128 + tid;
        int tile = id >> 9;
        int row  = (id >> 3) & 63;
        int ch   = id & 7;
        const __nv_bfloat16* src;
        if (tile == 0)
            src = g_kh + (((size_t)kv * T_SEQ + kb * 64 + row) * HD + ch * 8);
        else if (tile == 1)
            src = g_kl + (((size_t)kv * T_SEQ + kb * 64 + row) * HD + ch * 8);
        else if (tile == 2)
            src = g_vh + (((size_t)kv * HD + row) * T_SEQ + kb * 64 + ch * 8);
        else
            src = g_vl + (((size_t)kv * HD + row) * T_SEQ + kb * 64 + ch * 8);
        cp16(base + (tile * ATT_TILE + row * TSTR + ch * 8) * 2, src);
    }
    cp_commit();
}

__global__ __launch_bounds__(128)
void attn_mma_kernel() {
    __nv_bfloat16* att_dsm = (__nv_bfloat16*)dsm_raw;
    int h  = blockIdx.x;
    int qb = blockIdx.y;
    int kv = h >> 2;
    int tid  = threadIdx.x;
    int w    = tid >> 5;
    int lane = tid & 31;
    int qr   = lane >> 2;
    int qc2  = (lane & 3) * 2;
    int rowA = w * 16 + qr;

    // stage Q (fp32, pre-scaled) in stage-0 region, build A-frags, release
    float* sQ = (float*)att_dsm;
    for (int i = tid; i < 64 * 16; i += 128) {
        int row = i >> 4;
        int c4  = (i & 15) * 4;
        float4 v = *(const float4*)&g_q[(((size_t)qb * 64 + row) * NH + h) * HD + c4];
        v.x *= 0.125f; v.y *= 0.125f; v.z *= 0.125f; v.w *= 0.125f;
        *(float4*)&sQ[row * 68 + c4] = v;
    }
    __syncthreads();

    uint32_t qh[4][4], ql[4][4];
#pragma unroll
    for (int kc = 0; kc < 4; kc++) {
        int k = kc * 16 + qc2;
        cvt2(*(const float2*)&sQ[rowA * 68 + k],           qh[kc][0], ql[kc][0]);
        cvt2(*(const float2*)&sQ[(rowA + 8) * 68 + k],     qh[kc][1], ql[kc][1]);
        cvt2(*(const float2*)&sQ[rowA * 68 + k + 8],       qh[kc][2], ql[kc][2]);
        cvt2(*(const float2*)&sQ[(rowA + 8) * 68 + k + 8], qh[kc][3], ql[kc][3]);
    }
    __syncthreads();

    float m0 = -1e30f, m1 = -1e30f, l0 = 0.0f, l1 = 0.0f;
    float o[8][4];
#pragma unroll
    for (int ni = 0; ni < 8; ni++)
#pragma unroll
        for (int e = 0; e < 4; e++) o[ni][e] = 0.0f;

    int cur = 0, stage = 0;
    att_issue_loads(att_dsm, 0, 0, kv, tid);

    while (cur < NBLK) {
        int nxt = cur + 1;
        while (nxt < NBLK) {
            if (g_allow[qb * NBLK + nxt] || (nxt < 4) ||
                (nxt <= qb && nxt + 4 >= qb)) break;
            nxt++;
        }
        if (nxt < NBLK) {
            att_issue_loads(att_dsm, stage ^ 1, nxt, kv, tid);
            asm volatile("cp.async.wait_group 1;" ::: "memory");
        } else {
            asm volatile("cp.async.wait_group 0;" ::: "memory");
        }
        __syncthreads();

        int kb = cur;
        int ba = g_allow[qb * NBLK + kb];
        const __nv_bfloat16* sKh = att_dsm + stage * ATT_STAGE;
        const __nv_bfloat16* sKl = sKh + ATT_TILE;
        const __nv_bfloat16* sVh = sKl + ATT_TILE;
        const __nv_bfloat16* sVl = sVh + ATT_TILE;

        float s[8][4];
#pragma unroll
        for (int ni = 0; ni < 8; ni++) {
#pragma unroll
            for (int e = 0; e < 4; e++) s[ni][e] = 0.0f;
            int n = ni * 8 + qr;
#pragma unroll
            for (int kc = 0; kc < 4; kc++) {
                int kcol = kc * 16 + qc2;
                uint32_t bh0 = *(const uint32_t*)&sKh[n * TSTR + kcol];
                uint32_t bh1 = *(const uint32_t*)&sKh[n * TSTR + kcol + 8];
                uint32_t bl0 = *(const uint32_t*)&sKl[n * TSTR + kcol];
                uint32_t bl1 = *(const uint32_t*)&sKl[n * TSTR + kcol + 8];
                MMA_BF16(s[ni], qh[kc][0], qh[kc][1], qh[kc][2], qh[kc][3], bh0, bh1);
                MMA_BF16(s[ni], qh[kc][0], qh[kc][1], qh[kc][2], qh[kc][3], bl0, bl1);
                MMA_BF16(s[ni], ql[kc][0], ql[kc][1], ql[kc][2], ql[kc][3], bh0, bh1);
            }
        }

        int qi0 = qb * 64 + rowA;
        int qi1 = qi0 + 8;
#pragma unroll
        for (int ni = 0; ni < 8; ni++) {
            int col = kb * 64 + ni * 8 + qc2;
#pragma unroll
            for (int e = 0; e < 4; e++) {
                int kj = col + (e & 1);
                int qi = (e < 2) ? qi0 : qi1;
                bool ok = ba || (kj < WIN) || (kj <= qi && kj + (WIN - 1) >= qi);
                if (!ok) s[ni][e] = -1e30f;
            }
        }

        float mb0 = -1e30f, mb1 = -1e30f;
#pragma unroll
        for (int ni = 0; ni < 8; ni++) {
            mb0 = fmaxf(mb0, fmaxf(s[ni][0], s[ni][1]));
            mb1 = fmaxf(mb1, fmaxf(s[ni][2], s[ni][3]));
        }
        mb0 = fmaxf(mb0, __shfl_xor_sync(0xFFFFFFFF, mb0, 1));
        mb0 = fmaxf(mb0, __shfl_xor_sync(0xFFFFFFFF, mb0, 2));
        mb1 = fmaxf(mb1, __shfl_xor_sync(0xFFFFFFFF, mb1, 1));
        mb1 = fmaxf(mb1, __shfl_xor_sync(0xFFFFFFFF, mb1, 2));

        float mn0 = fmaxf(m0, mb0), mn1 = fmaxf(m1, mb1);
        float sc0 = __expf(m0 - mn0), sc1 = __expf(m1 - mn1);
        m0 = mn0; m1 = mn1;
        l0 *= sc0; l1 *= sc1;
#pragma unroll
        for (int ni = 0; ni < 8; ni++) {
            o[ni][0] *= sc0; o[ni][1] *= sc0;
            o[ni][2] *= sc1; o[ni][3] *= sc1;
        }

#pragma unroll
        for (int ni = 0; ni < 8; ni++) {
            s[ni][0] = __expf(s[ni][0] - m0);
            s[ni][1] = __expf(s[ni][1] - m0);
            s[ni][2] = __expf(s[ni][2] - m1);
            s[ni][3] = __expf(s[ni][3] - m1);
            l0 += s[ni][0] + s[ni][1];
            l1 += s[ni][2] + s[ni][3];
        }

#pragma unroll
        for (int kc = 0; kc < 4; kc++) {
            uint32_t ah[4], al[4];
            cvt2(make_float2(s[2 * kc][0],     s[2 * kc][1]),     ah[0], al[0]);
            cvt2(make_float2(s[2 * kc][2],     s[2 * kc][3]),     ah[1], al[1]);
            cvt2(make_float2(s[2 * kc + 1][0], s[2 * kc + 1][1]), ah[2], al[2]);
            cvt2(make_float2(s[2 * kc + 1][2], s[2 * kc + 1][3]), ah[3], al[3]);
#pragma unroll
            for (int ni = 0; ni < 8; ni++) {
                int n = ni * 8 + qr;
                int kcol = kc * 16 + qc2;
                uint32_t bh0 = *(const uint32_t*)&sVh[n * TSTR + kcol];
                uint32_t bh1 = *(const uint32_t*)&sVh[n * TSTR + kcol + 8];
                uint32_t bl0 = *(const uint32_t*)&sVl[n * TSTR + kcol];
                uint32_t bl1 = *(const uint32_t*)&sVl[n * TSTR + kcol + 8];
                MMA_BF16(o[ni], ah[0], ah[1], ah[2], ah[3], bh0, bh1);
                MMA_BF16(o[ni], ah[0], ah[1], ah[2], ah[3], bl0, bl1);
                MMA_BF16(o[ni], al[0], al[1], al[2], al[3], bh0, bh1);
            }
        }
        __syncthreads();
        cur = nxt;
        stage ^= 1;
    }

    l0 += __shfl_xor_sync(0xFFFFFFFF, l0, 1);
    l0 += __shfl_xor_sync(0xFFFFFFFF, l0, 2);
    l1 += __shfl_xor_sync(0xFFFFFFFF, l1, 1);
    l1 += __shfl_xor_sync(0xFFFFFFFF, l1, 2);
    float inv0 = 1.0f / l0, inv1 = 1.0f / l1;

    int qi0 = qb * 64 + rowA;
#pragma unroll
    for (int ni = 0; ni < 8; ni++) {
        int d = ni * 8 + qc2;
        uint32_t hi, lo;
        cvt2(make_float2(o[ni][0] * inv0, o[ni][1] * inv0), hi, lo);
        int idx0 = ((size_t)qi0 * EMB + h * HD + d) >> 1;
        ((uint32_t*)g_oh)[idx0] = hi;
        ((uint32_t*)g_ol)[idx0] = lo;
        cvt2(make_float2(o[ni][2] * inv1, o[ni][3] * inv1), hi, lo);
        int idx1 = ((size_t)(qi0 + 8) * EMB + h * HD + d) >> 1;
        ((uint32_t*)g_oh)[idx1] = hi;
        ((uint32_t*)g_ol)[idx1] = lo;
    }
}

// ---------------------------------------------------------------------------
extern "C" void kernel_launch(void* const* d_in, const int* in_sizes, int n_in,
                              void* d_out, int out_size) {
    const float* hs   = (const float*)d_in[0];
    const float* cosb = (const float*)d_in[1];
    const float* sinb = (const float*)d_in[2];
    const float* Wq   = (const float*)d_in[3];
    const float* Wk   = (const float*)d_in[4];
    const float* Wv   = (const float*)d_in[5];
    const float* Wo   = (const float*)d_in[6];
    const void*  allow = d_in[7];
    float* out = (float*)d_out;

    __nv_bfloat16 *hsh, *hsl, *wqh, *wql, *wkh, *wkl, *wvh, *wvl, *woh, *wol;
    cudaGetSymbolAddress((void**)&hsh, g_hsh);
    cudaGetSymbolAddress((void**)&hsl, g_hsl);
    cudaGetSymbolAddress((void**)&wqh, g_wqh);
    cudaGetSymbolAddress((void**)&wql, g_wql);
    cudaGetSymbolAddress((void**)&wkh, g_wkh);
    cudaGetSymbolAddress((void**)&wkl, g_wkl);
    cudaGetSymbolAddress((void**)&wvh, g_wvh);
    cudaGetSymbolAddress((void**)&wvl, g_wvl);
    cudaGetSymbolAddress((void**)&woh, g_woh);
    cudaGetSymbolAddress((void**)&wol, g_wol);

    cudaFuncSetAttribute(attn_mma_kernel,
                         cudaFuncAttributeMaxDynamicSharedMemorySize, ATT_SMEM);
    cudaFuncSetAttribute(qkv_gemm,
                         cudaFuncAttributeMaxDynamicSharedMemorySize, G5_SMEM);
    cudaFuncSetAttribute(out_gemm,
                         cudaFuncAttributeMaxDynamicSharedMemorySize, G5_SMEM);

    // one-time bf16 hi/lo conversion of GEMM operands
    {
        int n2 = T_SEQ * EMB / 2;
        cvt_hilo<<<(n2 + 255) / 256, 256>>>(hs, hsh, hsl, n2);
        n2 = EMB * EMB / 2;
        cvt_hilo<<<(n2 + 255) / 256, 256>>>(Wq, wqh, wql, n2);
        cvt_hilo<<<(n2 + 255) / 256, 256>>>(Wo, woh, wol, n2);
        n2 = KVD * EMB / 2;
        cvt_hilo<<<(n2 + 255) / 256, 256>>>(Wk, wkh, wkl, n2);
        cvt_hilo<<<(n2 + 255) / 256, 256>>>(Wv, wvh, wvl, n2);
    }

    // Fused QKV projection (128x256 tiles)
    qkv_gemm<<<dim3(12, T_SEQ / 128), 256, G5_SMEM>>>();

    // RoPE (q, k in place)
    {
        int total = T_SEQ * (NH + NKV) * 32;
        rope_kernel<<<(total + 255) / 256, 256>>>(cosb, sinb);
    }

    // Pre-convert K (post-RoPE) and V for attention
    prep_k_kernel<<<(NKV * T_SEQ * HD + 255) / 256, 256>>>();
    prep_v_kernel<<<(NKV * HD * T_SEQ + 255) / 256, 256>>>();

    // Mask decode (only needed before attention)
    decode_mask_kernel<<<1, 256>>>(allow);

    // MMA flash attention (double-buffered)
    attn_mma_kernel<<<dim3(NH, NBLK), 128, ATT_SMEM>>>();

    // Output projection
    out_gemm<<<dim3(EMB / 256, T_SEQ / 128), 256, G5_SMEM>>>(out);
}

// round 11
// speedup vs baseline: 1.1444x; 1.1444x over previous
#include <cuda_runtime.h>
#include <cuda_bf16.h>
#include <math.h>
#include <stdint.h>

// Problem constants (fixed by setup_inputs)
#define T_SEQ 2048
#define EMB   2048
#define NH    32
#define NKV   8
#define HD    64
#define NBLK  32
#define WIN   256
#define KVD   (NKV * HD)   // 512

// fp32 scratch
__device__ float g_q[T_SEQ * NH * HD];     // [t][h][d]
__device__ float g_k[T_SEQ * NKV * HD];    // [t][kv][d]
__device__ float g_v[T_SEQ * NKV * HD];
__device__ int   g_allow[NBLK * NBLK];

// bf16 hi/lo pre-converted operands
__device__ __nv_bfloat16 g_hsh[T_SEQ * EMB], g_hsl[T_SEQ * EMB];
__device__ __nv_bfloat16 g_wqh[EMB * EMB],  g_wql[EMB * EMB];
__device__ __nv_bfloat16 g_wkh[KVD * EMB],  g_wkl[KVD * EMB];
__device__ __nv_bfloat16 g_wvh[KVD * EMB],  g_wvl[KVD * EMB];
__device__ __nv_bfloat16 g_woh[EMB * EMB],  g_wol[EMB * EMB];
__device__ __nv_bfloat16 g_oh[T_SEQ * EMB], g_ol[T_SEQ * EMB];

// attention K/V bf16 hi/lo (K: [kv][t][d], V transposed: [kv][d][t])
__device__ __nv_bfloat16 g_kh[NKV * T_SEQ * HD], g_kl[NKV * T_SEQ * HD];
__device__ __nv_bfloat16 g_vh[NKV * HD * T_SEQ], g_vl[NKV * HD * T_SEQ];

// one extern-shared buffer shared by all dynamic-smem kernels
extern __shared__ char dsm_raw[];

// ---------------------------------------------------------------------------
// Decode rw_allow_blocks robustly (bool/int8 vs int32 vs float32).
// ---------------------------------------------------------------------------
__global__ void decode_mask_kernel(const void* p) {
    __shared__ int cnt0, cnt123;
    int tid = threadIdx.x;
    if (tid == 0) { cnt0 = 0; cnt123 = 0; }
    __syncthreads();
    const unsigned char* b = (const unsigned char*)p;
    int l0 = 0, l123 = 0;
    for (int i = tid; i < 1024; i += 256) {
        if (b[i]) { if ((i & 3) == 0) l0++; else l123++; }
    }
    atomicAdd(&cnt0, l0);
    atomicAdd(&cnt123, l123);
    __syncthreads();
    if (cnt123 == 0) {
        const int* a = (const int*)p;
        for (int i = tid; i < 1024; i += 256) g_allow[i] = (a[i] != 0);
    } else if (cnt0 == 0) {
        const float* a = (const float*)p;
        for (int i = tid; i < 1024; i += 256) g_allow[i] = (a[i] != 0.0f);
    } else {
        for (int i = tid; i < 1024; i += 256) g_allow[i] = (b[i] != 0);
    }
}

// ---------------------------------------------------------------------------
// Shared helpers
// ---------------------------------------------------------------------------
#define MMA_BF16(d, a0, a1, a2, a3, b0, b1)                                   \
    asm volatile(                                                             \
        "mma.sync.aligned.m16n8k16.row.col.f32.bf16.bf16.f32 "                \
        "{%0,%1,%2,%3}, {%4,%5,%6,%7}, {%8,%9}, {%0,%1,%2,%3};"               \
        : "+f"(d[0]), "+f"(d[1]), "+f"(d[2]), "+f"(d[3])                      \
        : "r"(a0), "r"(a1), "r"(a2), "r"(a3), "r"(b0), "r"(b1))

#define LDSM_X4(R0, R1, R2, R3, ADDR)                                         \
    asm volatile("ldmatrix.sync.aligned.m8n8.x4.shared.b16 {%0,%1,%2,%3}, [%4];" \
        : "=r"(R0), "=r"(R1), "=r"(R2), "=r"(R3) : "r"(ADDR))

#define LDSM_X2(R0, R1, ADDR)                                                 \
    asm volatile("ldmatrix.sync.aligned.m8n8.x2.shared.b16 {%0,%1}, [%2];"    \
        : "=r"(R0), "=r"(R1) : "r"(ADDR))

__device__ __forceinline__ void cp16(uint32_t saddr, const void* g) {
    asm volatile("cp.async.cg.shared.global [%0], [%1], 16;" :: "r"(saddr), "l"(g));
}
__device__ __forceinline__ void cp_commit() {
    asm volatile("cp.async.commit_group;" ::: "memory");
}

__device__ __forceinline__ void cvt2(float2 f, uint32_t& hi, uint32_t& lo) {
    __nv_bfloat162 h = __floats2bfloat162_rn(f.x, f.y);
    hi = *reinterpret_cast<uint32_t*>(&h);
    __nv_bfloat162 l = __floats2bfloat162_rn(f.x - __bfloat162float(h.x),
                                             f.y - __bfloat162float(h.y));
    lo = *reinterpret_cast<uint32_t*>(&l);
}

__device__ __forceinline__ uint32_t smem_u32(const void* p) {
    return (uint32_t)__cvta_generic_to_shared(p);
}

// fp32 -> bf16 hi/lo, 4 elements per thread
__global__ void cvt_hilo(const float* __restrict__ src,
                         __nv_bfloat16* __restrict__ h,
                         __nv_bfloat16* __restrict__ l, int n4) {
    int i = blockIdx.x * blockDim.x + threadIdx.x;
    if (i >= n4) return;
    float4 v = ((const float4*)src)[i];
    uint32_t h0, l0, h1, l1;
    cvt2(make_float2(v.x, v.y), h0, l0);
    cvt2(make_float2(v.z, v.w), h1, l1);
    ((uint2*)h)[i] = make_uint2(h0, h1);
    ((uint2*)l)[i] = make_uint2(l0, l1);
}

// ---------------------------------------------------------------------------
// GEMM (R9, best known): C = A * B^T, pre-split bf16 hi/lo, ldmatrix frags.
// Block 128x128, BK=32, dynamic smem (2 stages x 40KB), 2 CTAs/SM.
// ---------------------------------------------------------------------------
#define TPADH      40
#define G3_ROW_B   (TPADH * 2)              // 80 bytes
#define G3_TILE_B  (128 * G3_ROW_B)         // 10240
#define G3_STAGE_B (4 * G3_TILE_B)          // 40960
#define G3_SMEM    (2 * G3_STAGE_B)         // 81920

__device__ __forceinline__ void gemm3_core(
    const __nv_bfloat16* __restrict__ Ah, const __nv_bfloat16* __restrict__ Al,
    const __nv_bfloat16* __restrict__ Bh, const __nv_bfloat16* __restrict__ Bl,
    float* __restrict__ C, int K, int ldc, int m0, int n0)
{
    uint32_t sbase = smem_u32(dsm_raw);

    int tid  = threadIdx.x;
    int warp = tid >> 5;
    int lane = tid & 31;
    int wm = warp & 1;
    int wn = warp >> 1;
    int qr = lane >> 2;
    int qc2 = (lane & 3) * 2;

    float acc[4][4][4];
#pragma unroll
    for (int i = 0; i < 4; i++)
#pragma unroll
        for (int j = 0; j < 4; j++)
#pragma unroll
            for (int e = 0; e < 4; e++) acc[i][j][e] = 0.0f;

    const __nv_bfloat16* srcs[4];
    srcs[0] = Ah + (size_t)m0 * K;
    srcs[1] = Al + (size_t)m0 * K;
    srcs[2] = Bh + (size_t)n0 * K;
    srcs[3] = Bl + (size_t)n0 * K;

    int arow = wm * 64 + (lane & 7) + ((lane >> 3) & 1) * 8;
    uint32_t aOff = arow * G3_ROW_B + ((lane >> 4) & 1) * 16;
    int brow = wn * 32 + (lane & 7);
    uint32_t bOff = brow * G3_ROW_B + ((lane >> 3) & 1) * 16;

    const int NITER = K / 32;

    {
        uint32_t sb = sbase;
#pragma unroll
        for (int t = 0; t < 8; t++) {
            int id = t * 256 + tid;
            int tile = id >> 9;
            int row  = (id >> 2) & 127;
            int c    = id & 3;
            cp16(sb + tile * G3_TILE_B + row * G3_ROW_B + c * 16,
                 srcs[tile] + (size_t)row * K + c * 8);
        }
        cp_commit();
    }

    for (int it = 0; it < NITER; it++) {
        if (it + 1 < NITER) {
            int k0 = (it + 1) * 32;
            uint32_t sb = sbase + ((it + 1) & 1) * G3_STAGE_B;
#pragma unroll
            for (int t = 0; t < 8; t++) {
                int id = t * 256 + tid;
                int tile = id >> 9;
                int row  = (id >> 2) & 127;
                int c    = id & 3;
                cp16(sb + tile * G3_TILE_B + row * G3_ROW_B + c * 16,
                     srcs[tile] + (size_t)row * K + k0 + c * 8);
            }
            cp_commit();
            asm volatile("cp.async.wait_group 1;" ::: "memory");
        } else {
            asm volatile("cp.async.wait_group 0;" ::: "memory");
        }
        __syncthreads();

        uint32_t sb = sbase + (it & 1) * G3_STAGE_B;
        uint32_t tAh = sb, tAl = sb + G3_TILE_B;
        uint32_t tBh = sb + 2 * G3_TILE_B, tBl = sb + 3 * G3_TILE_B;

#pragma unroll
        for (int k1 = 0; k1 < 2; k1++) {
            uint32_t ko = k1 * 32;
            uint32_t ah[4][4], al[4][4];
#pragma unroll
            for (int mi = 0; mi < 4; mi++) {
                uint32_t off = aOff + mi * (16 * G3_ROW_B) + ko;
                LDSM_X4(ah[mi][0], ah[mi][1], ah[mi][2], ah[mi][3], tAh + off);
                LDSM_X4(al[mi][0], al[mi][1], al[mi][2], al[mi][3], tAl + off);
            }
#pragma unroll
            for (int ni = 0; ni < 4; ni++) {
                uint32_t off = bOff + ni * (8 * G3_ROW_B) + ko;
                uint32_t bh0, bh1, bl0, bl1;
                LDSM_X2(bh0, bh1, tBh + off);
                LDSM_X2(bl0, bl1, tBl + off);
#pragma unroll
                for (int mi = 0; mi < 4; mi++) {
                    MMA_BF16(acc[mi][ni], ah[mi][0], ah[mi][1], ah[mi][2], ah[mi][3], bh0, bh1);
                    MMA_BF16(acc[mi][ni], ah[mi][0], ah[mi][1], ah[mi][2], ah[mi][3], bl0, bl1);
                    MMA_BF16(acc[mi][ni], al[mi][0], al[mi][1], al[mi][2], al[mi][3], bh0, bh1);
                }
            }
        }
        __syncthreads();
    }

#pragma unroll
    for (int mi = 0; mi < 4; mi++) {
#pragma unroll
        for (int ni = 0; ni < 4; ni++) {
            int r = m0 + wm * 64 + mi * 16 + qr;
            int cidx = n0 + wn * 32 + ni * 8 + qc2;
            *(float2*)&C[(size_t)r * ldc + cidx] =
                make_float2(acc[mi][ni][0], acc[mi][ni][1]);
            *(float2*)&C[(size_t)(r + 8) * ldc + cidx] =
                make_float2(acc[mi][ni][2], acc[mi][ni][3]);
        }
    }
}

__global__ __launch_bounds__(256, 2)
void qkv_gemm() {
    int bx = blockIdx.x;
    int m0 = blockIdx.y * 128;
    if (bx < 16)
        gemm3_core(g_hsh, g_hsl, g_wqh, g_wql, g_q, EMB, EMB, m0, bx * 128);
    else if (bx < 20)
        gemm3_core(g_hsh, g_hsl, g_wkh, g_wkl, g_k, EMB, KVD, m0, (bx - 16) * 128);
    else
        gemm3_core(g_hsh, g_hsl, g_wvh, g_wvl, g_v, EMB, KVD, m0, (bx - 20) * 128);
}

__global__ __launch_bounds__(256, 2)
void out_gemm(float* __restrict__ out) {
    gemm3_core(g_oh, g_ol, g_woh, g_wol, out, EMB, EMB,
               blockIdx.y * 128, blockIdx.x * 128);
}

// ---------------------------------------------------------------------------
// RoPE applied in-place to q and k.
// ---------------------------------------------------------------------------
__global__ void rope_kernel(const float* __restrict__ cosb, const float* __restrict__ sinb) {
    int idx = blockIdx.x * blockDim.x + threadIdx.x;
    const int total = T_SEQ * (NH + NKV) * 32;
    if (idx >= total) return;
    int d = idx & 31;
    int rest = idx >> 5;
    int head = rest % (NH + NKV);
    int t = rest / (NH + NKV);
    float c0 = cosb[t * HD + d];
    float s0 = sinb[t * HD + d];
    float c1 = cosb[t * HD + d + 32];
    float s1 = sinb[t * HD + d + 32];
    float* base = (head < NH) ? (g_q + ((size_t)t * NH + head) * HD)
                              : (g_k + ((size_t)t * NKV + (head - NH)) * HD);
    float x0 = base[d];
    float x1 = base[d + 32];
    base[d]      = x0 * c0 - x1 * s0;
    base[d + 32] = x1 * c1 + x0 * s1;
}

// ---------------------------------------------------------------------------
// Fused prep: K -> bf16 hi/lo [kv][t][d]; V -> transposed [kv][d][t].
// ---------------------------------------------------------------------------
__global__ void prep_kv_kernel() {
    const int NK = NKV * T_SEQ * HD;
    int o = blockIdx.x * blockDim.x + threadIdx.x;
    if (o < NK) {
        int d  = o & 63;
        int t  = (o >> 6) & (T_SEQ - 1);
        int kv = o >> 17;
        float v = g_k[((size_t)t * NKV + kv) * HD + d];
        __nv_bfloat16 h = __float2bfloat16(v);
        g_kh[o] = h;
        g_kl[o] = __float2bfloat16(v - __bfloat162float(h));
    } else {
        o -= NK;
        if (o >= NK) return;
        int t  = o & (T_SEQ - 1);
        int d  = (o >> 11) & 63;
        int kv = o >> 17;
        float v = g_v[((size_t)t * NKV + kv) * HD + d];
        __nv_bfloat16 h = __float2bfloat16(v);
        g_vh[o] = h;
        g_vl[o] = __float2bfloat16(v - __bfloat162float(h));
    }
}

// ---------------------------------------------------------------------------
// MMA flash attention: double-buffered kb tiles, ldmatrix frag loads, exp2
// softmax (log2e folded into Q scale).
// ---------------------------------------------------------------------------
#define TSTR  72
#define TSTRB (TSTR * 2)                 // 144 bytes per tile row
#define ATT_TILE   (64 * TSTR)           // bf16 elems per tile
#define ATT_TILE_B (ATT_TILE * 2)
#define ATT_STAGE  (4 * ATT_TILE)
#define ATT_STAGE_B (ATT_STAGE * 2)
#define ATT_SMEM   (2 * ATT_STAGE_B)

__device__ __forceinline__ void att_issue_loads(__nv_bfloat16* att_dsm,
                                                int stage, int kb, int kv, int tid) {
    uint32_t base = smem_u32(att_dsm) + stage * ATT_STAGE_B;
#pragma unroll
    for (int t = 0; t < 16; t++) {
        int id   = t * 128 + tid;
        int tile = id >> 9;
        int row  = (id >> 3) & 63;
        int ch   = id & 7;
        const __nv_bfloat16* src;
        if (tile == 0)
            src = g_kh + (((size_t)kv * T_SEQ + kb * 64 + row) * HD + ch * 8);
        else if (tile == 1)
            src = g_kl + (((size_t)kv * T_SEQ + kb * 64 + row) * HD + ch * 8);
        else if (tile == 2)
            src = g_vh + (((size_t)kv * HD + row) * T_SEQ + kb * 64 + ch * 8);
        else
            src = g_vl + (((size_t)kv * HD + row) * T_SEQ + kb * 64 + ch * 8);
        cp16(base + tile * ATT_TILE_B + row * TSTRB + ch * 16, src);
    }
    cp_commit();
}

__global__ __launch_bounds__(128)
void attn_mma_kernel() {
    __nv_bfloat16* att_dsm = (__nv_bfloat16*)dsm_raw;
    int h  = blockIdx.x;
    int qb = blockIdx.y;
    int kv = h >> 2;
    int tid  = threadIdx.x;
    int w    = tid >> 5;
    int lane = tid & 31;
    int qr   = lane >> 2;
    int qc2  = (lane & 3) * 2;
    int rowA = w * 16 + qr;

    // stage Q (fp32, scale = 0.125 * log2(e)) in stage-0 region, build A-frags
    const float QSC = 0.125f * 1.4426950408889634f;
    float* sQ = (float*)att_dsm;
    for (int i = tid; i < 64 * 16; i += 128) {
        int row = i >> 4;
        int c4  = (i & 15) * 4;
        float4 v = *(const float4*)&g_q[(((size_t)qb * 64 + row) * NH + h) * HD + c4];
        v.x *= QSC; v.y *= QSC; v.z *= QSC; v.w *= QSC;
        *(float4*)&sQ[row * 68 + c4] = v;
    }
    __syncthreads();

    uint32_t qh[4][4], ql[4][4];
#pragma unroll
    for (int kc = 0; kc < 4; kc++) {
        int k = kc * 16 + qc2;
        cvt2(*(const float2*)&sQ[rowA * 68 + k],           qh[kc][0], ql[kc][0]);
        cvt2(*(const float2*)&sQ[(rowA + 8) * 68 + k],     qh[kc][1], ql[kc][1]);
        cvt2(*(const float2*)&sQ[rowA * 68 + k + 8],       qh[kc][2], ql[kc][2]);
        cvt2(*(const float2*)&sQ[(rowA + 8) * 68 + k + 8], qh[kc][3], ql[kc][3]);
    }
    __syncthreads();

    float m0 = -1e30f, m1 = -1e30f, l0 = 0.0f, l1 = 0.0f;
    float o[8][4];
#pragma unroll
    for (int ni = 0; ni < 8; ni++)
#pragma unroll
        for (int e = 0; e < 4; e++) o[ni][e] = 0.0f;

    // ldmatrix per-thread pattern within a tile
    uint32_t lanePat = (uint32_t)(lane & 7) * TSTRB + ((lane >> 3) & 1) * 16;
    uint32_t sbase = smem_u32(att_dsm);

    int cur = 0, stage = 0;
    att_issue_loads(att_dsm, 0, 0, kv, tid);

    while (cur < NBLK) {
        int nxt = cur + 1;
        while (nxt < NBLK) {
            if (g_allow[qb * NBLK + nxt] || (nxt < 4) ||
                (nxt <= qb && nxt + 4 >= qb)) break;
            nxt++;
        }
        if (nxt < NBLK) {
            att_issue_loads(att_dsm, stage ^ 1, nxt, kv, tid);
            asm volatile("cp.async.wait_group 1;" ::: "memory");
        } else {
            asm volatile("cp.async.wait_group 0;" ::: "memory");
        }
        __syncthreads();

        int kb = cur;
        int ba = g_allow[qb * NBLK + kb];
        uint32_t sb = sbase + stage * ATT_STAGE_B;
        uint32_t aKh = sb + lanePat;                       // K hi tile
        uint32_t aKl = aKh + ATT_TILE_B;                   // K lo
        uint32_t aVh = sb + 2 * ATT_TILE_B + lanePat;      // V hi
        uint32_t aVl = aVh + ATT_TILE_B;                   // V lo

        // ---- S = Q K^T (ldmatrix frags) ----
        float s[8][4];
#pragma unroll
        for (int ni = 0; ni < 8; ni++) {
#pragma unroll
            for (int e = 0; e < 4; e++) s[ni][e] = 0.0f;
#pragma unroll
            for (int kc = 0; kc < 4; kc++) {
                uint32_t off = ni * (8 * TSTRB) + kc * 32;
                uint32_t bh0, bh1, bl0, bl1;
                LDSM_X2(bh0, bh1, aKh + off);
                LDSM_X2(bl0, bl1, aKl + off);
                MMA_BF16(s[ni], qh[kc][0], qh[kc][1], qh[kc][2], qh[kc][3], bh0, bh1);
                MMA_BF16(s[ni], qh[kc][0], qh[kc][1], qh[kc][2], qh[kc][3], bl0, bl1);
                MMA_BF16(s[ni], ql[kc][0], ql[kc][1], ql[kc][2], ql[kc][3], bh0, bh1);
            }
        }

        // ---- mask ----
        int qi0 = qb * 64 + rowA;
        int qi1 = qi0 + 8;
#pragma unroll
        for (int ni = 0; ni < 8; ni++) {
            int col = kb * 64 + ni * 8 + qc2;
#pragma unroll
            for (int e = 0; e < 4; e++) {
                int kj = col + (e & 1);
                int qi = (e < 2) ? qi0 : qi1;
                bool ok = ba || (kj < WIN) || (kj <= qi && kj + (WIN - 1) >= qi);
                if (!ok) s[ni][e] = -1e30f;
            }
        }

        // ---- online softmax (base 2) ----
        float mb0 = -1e30f, mb1 = -1e30f;
#pragma unroll
        for (int ni = 0; ni < 8; ni++) {
            mb0 = fmaxf(mb0, fmaxf(s[ni][0], s[ni][1]));
            mb1 = fmaxf(mb1, fmaxf(s[ni][2], s[ni][3]));
        }
        mb0 = fmaxf(mb0, __shfl_xor_sync(0xFFFFFFFF, mb0, 1));
        mb0 = fmaxf(mb0, __shfl_xor_sync(0xFFFFFFFF, mb0, 2));
        mb1 = fmaxf(mb1, __shfl_xor_sync(0xFFFFFFFF, mb1, 1));
        mb1 = fmaxf(mb1, __shfl_xor_sync(0xFFFFFFFF, mb1, 2));

        float mn0 = fmaxf(m0, mb0), mn1 = fmaxf(m1, mb1);
        float sc0 = exp2f(m0 - mn0), sc1 = exp2f(m1 - mn1);
        m0 = mn0; m1 = mn1;
        l0 *= sc0; l1 *= sc1;
#pragma unroll
        for (int ni = 0; ni < 8; ni++) {
            o[ni][0] *= sc0; o[ni][1] *= sc0;
            o[ni][2] *= sc1; o[ni][3] *= sc1;
        }

#pragma unroll
        for (int ni = 0; ni < 8; ni++) {
            s[ni][0] = exp2f(s[ni][0] - m0);
            s[ni][1] = exp2f(s[ni][1] - m0);
            s[ni][2] = exp2f(s[ni][2] - m1);
            s[ni][3] = exp2f(s[ni][3] - m1);
            l0 += s[ni][0] + s[ni][1];
            l1 += s[ni][2] + s[ni][3];
        }

        // ---- O += P V (ldmatrix frags for V) ----
#pragma unroll
        for (int kc = 0; kc < 4; kc++) {
            uint32_t ah[4], al[4];
            cvt2(make_float2(s[2 * kc][0],     s[2 * kc][1]),     ah[0], al[0]);
            cvt2(make_float2(s[2 * kc][2],     s[2 * kc][3]),     ah[1], al[1]);
            cvt2(make_float2(s[2 * kc + 1][0], s[2 * kc + 1][1]), ah[2], al[2]);
            cvt2(make_float2(s[2 * kc + 1][2], s[2 * kc + 1][3]), ah[3], al[3]);
#pragma unroll
            for (int ni = 0; ni < 8; ni++) {
                uint32_t off = ni * (8 * TSTRB) + kc * 32;
                uint32_t bh0, bh1, bl0, bl1;
                LDSM_X2(bh0, bh1, aVh + off);
                LDSM_X2(bl0, bl1, aVl + off);
                MMA_BF16(o[ni], ah[0], ah[1], ah[2], ah[3], bh0, bh1);
                MMA_BF16(o[ni], ah[0], ah[1], ah[2], ah[3], bl0, bl1);
                MMA_BF16(o[ni], al[0], al[1], al[2], al[3], bh0, bh1);
            }
        }
        __syncthreads();
        cur = nxt;
        stage ^= 1;
    }

    l0 += __shfl_xor_sync(0xFFFFFFFF, l0, 1);
    l0 += __shfl_xor_sync(0xFFFFFFFF, l0, 2);
    l1 += __shfl_xor_sync(0xFFFFFFFF, l1, 1);
    l1 += __shfl_xor_sync(0xFFFFFFFF, l1, 2);
    float inv0 = 1.0f / l0, inv1 = 1.0f / l1;

    int qi0 = qb * 64 + rowA;
#pragma unroll
    for (int ni = 0; ni < 8; ni++) {
        int d = ni * 8 + qc2;
        uint32_t hi, lo;
        cvt2(make_float2(o[ni][0] * inv0, o[ni][1] * inv0), hi, lo);
        int idx0 = ((size_t)qi0 * EMB + h * HD + d) >> 1;
        ((uint32_t*)g_oh)[idx0] = hi;
        ((uint32_t*)g_ol)[idx0] = lo;
        cvt2(make_float2(o[ni][2] * inv1, o[ni][3] * inv1), hi, lo);
        int idx1 = ((size_t)(qi0 + 8) * EMB + h * HD + d) >> 1;
        ((uint32_t*)g_oh)[idx1] = hi;
        ((uint32_t*)g_ol)[idx1] = lo;
    }
}

// ---------------------------------------------------------------------------
extern "C" void kernel_launch(void* const* d_in, const int* in_sizes, int n_in,
                              void* d_out, int out_size) {
    const float* hs   = (const float*)d_in[0];
    const float* cosb = (const float*)d_in[1];
    const float* sinb = (const float*)d_in[2];
    const float* Wq   = (const float*)d_in[3];
    const float* Wk   = (const float*)d_in[4];
    const float* Wv   = (const float*)d_in[5];
    const float* Wo   = (const float*)d_in[6];
    const void*  allow = d_in[7];
    float* out = (float*)d_out;

    __nv_bfloat16 *hsh, *hsl, *wqh, *wql, *wkh, *wkl, *wvh, *wvl, *woh, *wol;
    cudaGetSymbolAddress((void**)&hsh, g_hsh);
    cudaGetSymbolAddress((void**)&hsl, g_hsl);
    cudaGetSymbolAddress((void**)&wqh, g_wqh);
    cudaGetSymbolAddress((void**)&wql, g_wql);
    cudaGetSymbolAddress((void**)&wkh, g_wkh);
    cudaGetSymbolAddress((void**)&wkl, g_wkl);
    cudaGetSymbolAddress((void**)&wvh, g_wvh);
    cudaGetSymbolAddress((void**)&wvl, g_wvl);
    cudaGetSymbolAddress((void**)&woh, g_woh);
    cudaGetSymbolAddress((void**)&wol, g_wol);

    cudaFuncSetAttribute(attn_mma_kernel,
                         cudaFuncAttributeMaxDynamicSharedMemorySize, ATT_SMEM);
    cudaFuncSetAttribute(qkv_gemm,
                         cudaFuncAttributeMaxDynamicSharedMemorySize, G3_SMEM);
    cudaFuncSetAttribute(out_gemm,
                         cudaFuncAttributeMaxDynamicSharedMemorySize, G3_SMEM);

    // one-time bf16 hi/lo conversion of GEMM operands (4 elems/thread)
    {
        int n4 = T_SEQ * EMB / 4;
        cvt_hilo<<<(n4 + 255) / 256, 256>>>(hs, hsh, hsl, n4);
        n4 = EMB * EMB / 4;
        cvt_hilo<<<(n4 + 255) / 256, 256>>>(Wq, wqh, wql, n4);
        cvt_hilo<<<(n4 + 255) / 256, 256>>>(Wo, woh, wol, n4);
        n4 = KVD * EMB / 4;
        cvt_hilo<<<(n4 + 255) / 256, 256>>>(Wk, wkh, wkl, n4);
        cvt_hilo<<<(n4 + 255) / 256, 256>>>(Wv, wvh, wvl, n4);
    }

    // Fused QKV projection
    qkv_gemm<<<dim3(24, T_SEQ / 128), 256, G3_SMEM>>>();

    // RoPE (q, k in place)
    {
        int total = T_SEQ * (NH + NKV) * 32;
        rope_kernel<<<(total + 255) / 256, 256>>>(cosb, sinb);
    }

    // Pre-convert K (post-RoPE) and V for attention (fused)
    prep_kv_kernel<<<(2 * NKV * T_SEQ * HD + 255) / 256, 256>>>();

    // Mask decode (only needed before attention)
    decode_mask_kernel<<<1, 256>>>(allow);

    // MMA flash attention (double-buffered, ldmatrix, exp2)
    attn_mma_kernel<<<dim3(NH, NBLK), 128, ATT_SMEM>>>();

    // Output projection
    out_gemm<<<dim3(EMB / 128, T_SEQ / 128), 256, G3_SMEM>>>(out);
}